// round 14
// baseline (speedup 1.0000x reference)
#include <cuda_runtime.h>
#include <cuda_fp16.h>
#include <cstdint>

// ---------------- problem dims ----------------
#define B_SZ 16384
#define D_SZ 512
#define O_SZ 512

// GEMM: 32 sparse k-iters (128 logical k, 64 stored) + 8 dense (64 k each)
#define NSP 32
#define NDN 8
#define NKIT (NSP + NDN)
#define NTHREADS 256
#define STAGES 3
#define BM 128
#define BN 64
#define SA_BYTES 16384                        // 128 rows x 128B
#define SB_BYTES 16384                        // sparse: 128 mem-rows x 128B; dense uses 8KB
#define SMETA_BYTES 2048
#define STAGE_BYTES (SA_BYTES + SB_BYTES + SMETA_BYTES)   // 34 KB
#define SMEM_BYTES (STAGES * STAGE_BYTES)                 // 102 KB (x2 CTAs/SM)

// ---------------- scratch ----------------
__device__ __half   g_As[(size_t)B_SZ * 512];        // silu panel
__device__ __half   g_Ab[(size_t)B_SZ * 2048];       // compressed 2:4 basis
__device__ uint8_t  g_metaB[(size_t)B_SZ * 512];     // meta byte per element
__device__ uint32_t g_metaP[(size_t)256 * 1024 * 8]; // [k16][M16][q] packed meta words
__device__ __half   g_Ws[(size_t)O_SZ * 512];        // base weights
__device__ __half   g_Wb[(size_t)O_SZ * 4096];       // permuted spline weights

// ---------------- helpers ----------------
__device__ __forceinline__ uint32_t smem_u32(const void* p) {
    return (uint32_t)__cvta_generic_to_shared(p);
}
__device__ __forceinline__ void cp_async16(uint32_t saddr, const void* g) {
    asm volatile("cp.async.cg.shared.global [%0], [%1], 16;" :: "r"(saddr), "l"(g) : "memory");
}
__device__ __forceinline__ void cp_commit() {
    asm volatile("cp.async.commit_group;" ::: "memory");
}
template <int N> __device__ __forceinline__ void cp_wait() {
    asm volatile("cp.async.wait_group %0;" :: "n"(N) : "memory");
}
__device__ __forceinline__ void ldsm_x4(uint32_t& r0, uint32_t& r1, uint32_t& r2, uint32_t& r3,
                                        uint32_t addr) {
    asm volatile("ldmatrix.sync.aligned.m8n8.x4.shared.b16 {%0,%1,%2,%3}, [%4];"
                 : "=r"(r0), "=r"(r1), "=r"(r2), "=r"(r3) : "r"(addr));
}
__device__ __forceinline__ void mma16816(float& c0, float& c1, float& c2, float& c3,
                                         uint32_t a0, uint32_t a1, uint32_t a2, uint32_t a3,
                                         uint32_t b0, uint32_t b1) {
    asm volatile(
        "mma.sync.aligned.m16n8k16.row.col.f32.f16.f16.f32 "
        "{%0,%1,%2,%3}, {%4,%5,%6,%7}, {%8,%9}, {%0,%1,%2,%3};"
        : "+f"(c0), "+f"(c1), "+f"(c2), "+f"(c3)
        : "r"(a0), "r"(a1), "r"(a2), "r"(a3), "r"(b0), "r"(b1));
}
__device__ __forceinline__ void mma_sp(float& c0, float& c1, float& c2, float& c3,
                                       uint32_t a0, uint32_t a1, uint32_t a2, uint32_t a3,
                                       uint32_t b0, uint32_t b1, uint32_t b2, uint32_t b3,
                                       uint32_t e) {
    asm volatile(
        "mma.sp::ordered_metadata.sync.aligned.m16n8k32.row.col.f32.f16.f16.f32 "
        "{%0,%1,%2,%3}, {%4,%5,%6,%7}, {%8,%9,%10,%11}, {%0,%1,%2,%3}, %12, 0x0;"
        : "+f"(c0), "+f"(c1), "+f"(c2), "+f"(c3)
        : "r"(a0), "r"(a1), "r"(a2), "r"(a3),
          "r"(b0), "r"(b1), "r"(b2), "r"(b3), "r"(e));
}
#define SWZ(o) ((o) ^ (((o) >> 3) & 0x70))

// ============================================================================
// gen_A: silu panel + 2:4-compressed basis + per-element metadata byte.
// Slot permutation p = 2(c&3)+(c>>2); compressed values = rot-left of
// [b0..b3] by 16*(t&3) bits, tail-masked for t>=5.
// ============================================================================
__global__ __launch_bounds__(256) void gen_A_kernel(const float* __restrict__ x) {
    int j = threadIdx.x & 63;
    int row = blockIdx.x * 4 + (threadIdx.x >> 6);
    const float* xrow = x + (size_t)row * D_SZ;
    const uint64_t META_TAB = 0xD4D4DDDD9D8D8988ull;   // byte t = meta(t)

#pragma unroll
    for (int e = 0; e < 8; ++e) {
        int i = j + 64 * e;
        float v = xrow[i];
        g_As[(size_t)row * 512 + i] = __float2half(__fdividef(v, 1.0f + __expf(-v)));

        float xc = fminf(fmaxf(v, -2.0f), 2.0f);
        float tpos = (xc + 2.0f) * 2.5f;        // [0, 10]
        bool valid = tpos < 8.0f;
        int t = min((int)tpos, 7);
        float u = tpos - (float)t;
        float um = 1.0f - u;
        float u2 = u * u, u3 = u2 * u;
        float b0 = um * um * um * (1.0f / 6.0f);
        float b1 = (3.0f * u3 - 6.0f * u2 + 4.0f) * (1.0f / 6.0f);
        float b2 = (-3.0f * u3 + 3.0f * u2 + 3.0f * u + 1.0f) * (1.0f / 6.0f);
        float b3 = u3 * (1.0f / 6.0f);

        __half2 p01 = __floats2half2_rn(b0, b1);
        __half2 p23 = __floats2half2_rn(b2, b3);
        uint64_t v64 = (uint64_t)reinterpret_cast<uint32_t&>(p01) |
                       ((uint64_t)reinterpret_cast<uint32_t&>(p23) << 32);
        int sh = (t & 3) * 16;
        uint64_t rot = sh ? ((v64 << sh) | (v64 >> (64 - sh))) : v64;
        if (t >= 5) rot &= (~0ull) << ((t - 4) * 16);
        uint8_t meta = 0x44;
        if (valid) meta = (uint8_t)(META_TAB >> (t * 8));
        else       rot = 0ull;

        *reinterpret_cast<uint2*>(g_Ab + (size_t)row * 2048 + (size_t)i * 4) =
            make_uint2((uint32_t)rot, (uint32_t)(rot >> 32));
        g_metaB[(size_t)row * 512 + i] = meta;
    }
}

// ============================================================================
// gen_W: base panel + permuted spline panel (Wb[o][i*8+p] = sp[(p&1)*4+(p>>1)])
// ============================================================================
__global__ void gen_W_kernel(const float* __restrict__ bw, const float* __restrict__ sw) {
    int o = blockIdx.x;
    int i = threadIdx.x;
    g_Ws[(size_t)o * 512 + i] = __float2half(bw[(size_t)o * 512 + i]);
    const float* sp = sw + ((size_t)o * 512 + i) * 8;
    __half h[8];
#pragma unroll
    for (int p = 0; p < 8; ++p) h[p] = __float2half(sp[(p & 1) * 4 + (p >> 1)]);
    *reinterpret_cast<uint4*>(g_Wb + (size_t)o * 4096 + (size_t)i * 8) =
        *reinterpret_cast<const uint4*>(h);
}

// ============================================================================
// meta_pack: g_metaB[b][i] -> g_metaP[(k16*1024 + M16)*8 + q]
// ============================================================================
__global__ __launch_bounds__(256) void meta_pack_kernel() {
    int g = blockIdx.x * 256 + threadIdx.x;     // 262144 total
    int k16 = g & 255, M16 = g >> 8;
    uint32_t w[8];
#pragma unroll
    for (int q = 0; q < 8; ++q) {
        int b0 = M16 * 16 + q;
        uint32_t lo = *reinterpret_cast<const uint16_t*>(g_metaB + (size_t)b0 * 512 + k16 * 2);
        uint32_t hi = *reinterpret_cast<const uint16_t*>(g_metaB + (size_t)(b0 + 8) * 512 + k16 * 2);
        w[q] = lo | (hi << 16);
    }
    uint32_t* dst = g_metaP + ((size_t)k16 * 1024 + M16) * 8;
    *reinterpret_cast<uint4*>(dst)     = make_uint4(w[0], w[1], w[2], w[3]);
    *reinterpret_cast<uint4*>(dst + 4) = make_uint4(w[4], w[5], w[6], w[7]);
}

// ============================================================================
// GEMM: CTA 128x64, 8 warps (warp tile 32x32, 4M x 2N), 3-stage, 2 CTAs/SM.
// ============================================================================
__device__ __forceinline__ void load_stage_sp(uint32_t sb, int s, int kt,
                                              int mbase, int nbase, int tid) {
    uint32_t stage = sb + s * STAGE_BYTES;
    const __half* agp = g_Ab + (size_t)mbase * 2048 + kt * 64;
#pragma unroll
    for (int it = 0; it < 4; ++it) {
        int c = tid + it * NTHREADS;
        int row = c >> 3, col = c & 7;
        cp_async16(stage + SWZ((uint32_t)(row * 128 + col * 16)),
                   agp + (size_t)row * 2048 + col * 8);
    }
    uint32_t bb = stage + SA_BYTES;
#pragma unroll
    for (int it = 0; it < 4; ++it) {          // 128 mem-rows x 128B
        int c = tid + it * NTHREADS;
        int r = c >> 3, col = c & 7;
        cp_async16(bb + SWZ((uint32_t)(r * 128 + col * 16)),
                   g_Wb + (size_t)(nbase + (r >> 1)) * 4096 + kt * 128 + (r & 1) * 64 + col * 8);
    }
    if (tid < 128) {
        int k16 = tid >> 4, inner = tid & 15;
        const char* src = (const char*)(g_metaP + ((size_t)(kt * 8 + k16) * 1024 + (mbase >> 4)) * 8)
                          + inner * 16;
        cp_async16(stage + SA_BYTES + SB_BYTES + tid * 16, src);
    }
}

__device__ __forceinline__ void load_stage_dn(uint32_t sb, int s, int ktd,
                                              int mbase, int nbase, int tid) {
    uint32_t stage = sb + s * STAGE_BYTES;
#pragma unroll
    for (int it = 0; it < 4; ++it) {
        int c = tid + it * NTHREADS;
        int row = c >> 3, col = c & 7;
        cp_async16(stage + SWZ((uint32_t)(row * 128 + col * 16)),
                   g_As + (size_t)(mbase + row) * 512 + ktd * 64 + col * 8);
    }
    uint32_t bb = stage + SA_BYTES;
#pragma unroll
    for (int it = 0; it < 2; ++it) {          // 64 rows x 128B
        int c = tid + it * NTHREADS;
        int row = c >> 3, col = c & 7;
        cp_async16(bb + SWZ((uint32_t)(row * 128 + col * 16)),
                   g_Ws + (size_t)(nbase + row) * 512 + ktd * 64 + col * 8);
    }
}

__global__ __launch_bounds__(NTHREADS, 2) void kan_gemm_kernel(float* __restrict__ out) {
    extern __shared__ __align__(1024) char smem[];
    uint32_t sb = smem_u32(smem);
    int tid = threadIdx.x, wid = tid >> 5, lane = tid & 31;
    int mbase = blockIdx.y * BM, nbase = blockIdx.x * BN;
    int warp_m = wid & 3;            // 4 warp-rows of 32
    int warp_n = wid >> 2;           // 2 warp-cols of 32

    float acc[2][4][4];
#pragma unroll
    for (int i = 0; i < 2; ++i)
#pragma unroll
        for (int jj = 0; jj < 4; ++jj)
#pragma unroll
            for (int q = 0; q < 4; ++q) acc[i][jj][q] = 0.0f;

    int a_row_in_tile = (lane & 7) + ((lane >> 3) & 1) * 8;
    int a_byte = (lane >> 4) * 16;
    int b_row_in_pair = (lane & 7) + (lane >> 4) * 8;
    int b_byte = ((lane >> 3) & 1) * 16;
    int qid = lane >> 2, tp1 = lane & 1;

#pragma unroll
    for (int p = 0; p < STAGES - 1; ++p) { load_stage_sp(sb, p, p, mbase, nbase, tid); cp_commit(); }

    for (int kt = 0; kt < NKIT; ++kt) {
        int s = kt % STAGES;
        cp_wait<STAGES - 2>();
        __syncthreads();
        int kload = kt + STAGES - 1;
        if (kload < NKIT) {
            if (kload < NSP) load_stage_sp(sb, kload % STAGES, kload, mbase, nbase, tid);
            else             load_stage_dn(sb, kload % STAGES, kload - NSP, mbase, nbase, tid);
        }
        cp_commit();

        uint32_t astage = sb + s * STAGE_BYTES;
        uint32_t bstage = astage + SA_BYTES;
        if (kt < NSP) {
            uint32_t mstage = astage + SA_BYTES + SB_BYTES;
#pragma unroll
            for (int j = 0; j < 4; ++j) {
                uint32_t a[2][4];
#pragma unroll
                for (int mt = 0; mt < 2; ++mt) {
                    int row = warp_m * 32 + mt * 16 + a_row_in_tile;
                    ldsm_x4(a[mt][0], a[mt][1], a[mt][2], a[mt][3],
                            astage + SWZ((uint32_t)(row * 128 + j * 32 + a_byte)));
                }
                uint32_t b[4][4];
#pragma unroll
                for (int pr = 0; pr < 2; ++pr) {
                    int rm = (warp_n * 32 + pr * 16 + b_row_in_pair) * 2 + (j >> 1);
                    uint32_t kb = (uint32_t)((j & 1) * 64 + b_byte);
                    uint32_t l0, l1, l2, l3, h0, h1, h2, h3;
                    ldsm_x4(l0, l1, l2, l3, bstage + SWZ((uint32_t)(rm * 128) + kb));
                    ldsm_x4(h0, h1, h2, h3, bstage + SWZ((uint32_t)(rm * 128) + kb + 32));
                    b[pr * 2 + 0][0] = l0; b[pr * 2 + 0][1] = l1;
                    b[pr * 2 + 0][2] = h0; b[pr * 2 + 0][3] = h1;
                    b[pr * 2 + 1][0] = l2; b[pr * 2 + 1][1] = l3;
                    b[pr * 2 + 1][2] = h2; b[pr * 2 + 1][3] = h3;
                }
#pragma unroll
                for (int mt = 0; mt < 2; ++mt) {
                    int m16c = warp_m * 2 + mt;
                    uint32_t em;
                    uint32_t widx = (uint32_t)((((j * 2 + tp1) * 8 + m16c) * 8 + qid) * 4);
                    asm volatile("ld.shared.b32 %0, [%1];" : "=r"(em) : "r"(mstage + widx));
#pragma unroll
                    for (int nt = 0; nt < 4; ++nt)
                        mma_sp(acc[mt][nt][0], acc[mt][nt][1], acc[mt][nt][2], acc[mt][nt][3],
                               a[mt][0], a[mt][1], a[mt][2], a[mt][3],
                               b[nt][0], b[nt][1], b[nt][2], b[nt][3], em);
                }
            }
        } else {
#pragma unroll
            for (int ks = 0; ks < 4; ++ks) {
                int kbyte = ks * 32;
                uint32_t a[2][4];
#pragma unroll
                for (int mt = 0; mt < 2; ++mt) {
                    int row = warp_m * 32 + mt * 16 + a_row_in_tile;
                    ldsm_x4(a[mt][0], a[mt][1], a[mt][2], a[mt][3],
                            astage + SWZ((uint32_t)(row * 128 + kbyte + a_byte)));
                }
                uint32_t b[4][2];
#pragma unroll
                for (int pr = 0; pr < 2; ++pr) {
                    int row = warp_n * 32 + pr * 16 + b_row_in_pair;
                    uint32_t r0, r1, r2, r3;
                    ldsm_x4(r0, r1, r2, r3, bstage + SWZ((uint32_t)(row * 128 + kbyte + b_byte)));
                    b[pr * 2 + 0][0] = r0; b[pr * 2 + 0][1] = r1;
                    b[pr * 2 + 1][0] = r2; b[pr * 2 + 1][1] = r3;
                }
#pragma unroll
                for (int mt = 0; mt < 2; ++mt)
#pragma unroll
                    for (int nt = 0; nt < 4; ++nt)
                        mma16816(acc[mt][nt][0], acc[mt][nt][1], acc[mt][nt][2], acc[mt][nt][3],
                                 a[mt][0], a[mt][1], a[mt][2], a[mt][3],
                                 b[nt][0], b[nt][1]);
            }
        }
    }

    int r0 = mbase + warp_m * 32 + (lane >> 2);
    int c0 = nbase + warp_n * 32 + (lane & 3) * 2;
#pragma unroll
    for (int mt = 0; mt < 2; ++mt) {
#pragma unroll
        for (int nt = 0; nt < 4; ++nt) {
            float* p = out + (size_t)(r0 + mt * 16) * O_SZ + c0 + nt * 8;
            *reinterpret_cast<float2*>(p) = make_float2(acc[mt][nt][0], acc[mt][nt][1]);
            float* p2 = p + 8 * O_SZ;
            *reinterpret_cast<float2*>(p2) = make_float2(acc[mt][nt][2], acc[mt][nt][3]);
        }
    }
}

// ============================================================================
extern "C" void kernel_launch(void* const* d_in, const int* in_sizes, int n_in,
                              void* d_out, int out_size) {
    const float* x  = (const float*)d_in[0];
    const float* bw = (const float*)d_in[1];
    const float* sw = (const float*)d_in[2];
    float* out = (float*)d_out;

    cudaFuncSetAttribute(kan_gemm_kernel,
                         cudaFuncAttributeMaxDynamicSharedMemorySize, SMEM_BYTES);

    gen_A_kernel<<<B_SZ / 4, 256>>>(x);
    gen_W_kernel<<<O_SZ, 512>>>(bw, sw);
    meta_pack_kernel<<<1024, 256>>>();

    dim3 grid(O_SZ / BN, B_SZ / BM);   // (8, 128)
    kan_gemm_kernel<<<grid, NTHREADS, SMEM_BYTES>>>(out);
}

// round 15
// speedup vs baseline: 1.1031x; 1.1031x over previous
#include <cuda_runtime.h>
#include <cuda_fp16.h>
#include <cstdint>

// ---------------- problem dims ----------------
#define B_SZ 16384
#define D_SZ 512
#define O_SZ 512

// GEMM: 32 sparse k-iters (128 logical k, 64 stored) + 8 dense (64 k each)
#define NSP 32
#define NDN 8
#define NKIT (NSP + NDN)
#define NTHREADS 512
#define STAGES 3
#define BM 256
#define BN 128
#define SA_BYTES 32768                        // 256 rows x 128B (compressed A / dense A)
#define SB_BYTES 32768                        // sparse: 256 mem-rows x 128B; dense uses 16KB
#define SMETA_BYTES 4096                      // 8 k16 x 16 M16 x 8 q words
#define STAGE_BYTES (SA_BYTES + SB_BYTES + SMETA_BYTES)   // 68 KB
#define SMEM_BYTES (STAGES * STAGE_BYTES)                 // 204 KB, 1 CTA/SM

// ---------------- scratch ----------------
__device__ __half   g_As[(size_t)B_SZ * 512];        // silu panel
__device__ __half   g_Ab[(size_t)B_SZ * 2048];       // compressed 2:4 basis
__device__ uint8_t  g_metaB[(size_t)B_SZ * 512];     // meta byte per element
__device__ uint32_t g_metaP[(size_t)256 * 1024 * 8]; // [k16][M16][q] packed meta words
__device__ __half   g_Ws[(size_t)O_SZ * 512];        // base weights
__device__ __half   g_Wb[(size_t)O_SZ * 4096];       // permuted spline weights

// ---------------- helpers ----------------
__device__ __forceinline__ uint32_t smem_u32(const void* p) {
    return (uint32_t)__cvta_generic_to_shared(p);
}
__device__ __forceinline__ void cp_async16(uint32_t saddr, const void* g) {
    asm volatile("cp.async.cg.shared.global [%0], [%1], 16;" :: "r"(saddr), "l"(g) : "memory");
}
__device__ __forceinline__ void cp_commit() {
    asm volatile("cp.async.commit_group;" ::: "memory");
}
template <int N> __device__ __forceinline__ void cp_wait() {
    asm volatile("cp.async.wait_group %0;" :: "n"(N) : "memory");
}
__device__ __forceinline__ void ldsm_x4(uint32_t& r0, uint32_t& r1, uint32_t& r2, uint32_t& r3,
                                        uint32_t addr) {
    asm volatile("ldmatrix.sync.aligned.m8n8.x4.shared.b16 {%0,%1,%2,%3}, [%4];"
                 : "=r"(r0), "=r"(r1), "=r"(r2), "=r"(r3) : "r"(addr));
}
__device__ __forceinline__ void mma16816(float& c0, float& c1, float& c2, float& c3,
                                         uint32_t a0, uint32_t a1, uint32_t a2, uint32_t a3,
                                         uint32_t b0, uint32_t b1) {
    asm volatile(
        "mma.sync.aligned.m16n8k16.row.col.f32.f16.f16.f32 "
        "{%0,%1,%2,%3}, {%4,%5,%6,%7}, {%8,%9}, {%0,%1,%2,%3};"
        : "+f"(c0), "+f"(c1), "+f"(c2), "+f"(c3)
        : "r"(a0), "r"(a1), "r"(a2), "r"(a3), "r"(b0), "r"(b1));
}
__device__ __forceinline__ void mma_sp(float& c0, float& c1, float& c2, float& c3,
                                       uint32_t a0, uint32_t a1, uint32_t a2, uint32_t a3,
                                       uint32_t b0, uint32_t b1, uint32_t b2, uint32_t b3,
                                       uint32_t e) {
    asm volatile(
        "mma.sp::ordered_metadata.sync.aligned.m16n8k32.row.col.f32.f16.f16.f32 "
        "{%0,%1,%2,%3}, {%4,%5,%6,%7}, {%8,%9,%10,%11}, {%0,%1,%2,%3}, %12, 0x0;"
        : "+f"(c0), "+f"(c1), "+f"(c2), "+f"(c3)
        : "r"(a0), "r"(a1), "r"(a2), "r"(a3),
          "r"(b0), "r"(b1), "r"(b2), "r"(b3), "r"(e));
}
#define SWZ(o) ((o) ^ (((o) >> 3) & 0x70))

// ============================================================================
// gen_A: silu panel + 2:4-compressed basis + per-element metadata byte.
// Slot permutation p = 2(c&3)+(c>>2); compressed values = rot-left of
// [b0..b3] by 16*(t&3) bits, tail-masked for t>=5.   (validated R13/R14)
// ============================================================================
__global__ __launch_bounds__(256) void gen_A_kernel(const float* __restrict__ x) {
    int j = threadIdx.x & 63;
    int row = blockIdx.x * 4 + (threadIdx.x >> 6);
    const float* xrow = x + (size_t)row * D_SZ;
    const uint64_t META_TAB = 0xD4D4DDDD9D8D8988ull;

#pragma unroll
    for (int e = 0; e < 8; ++e) {
        int i = j + 64 * e;
        float v = xrow[i];
        g_As[(size_t)row * 512 + i] = __float2half(__fdividef(v, 1.0f + __expf(-v)));

        float xc = fminf(fmaxf(v, -2.0f), 2.0f);
        float tpos = (xc + 2.0f) * 2.5f;        // [0, 10]
        bool valid = tpos < 8.0f;
        int t = min((int)tpos, 7);
        float u = tpos - (float)t;
        float um = 1.0f - u;
        float u2 = u * u, u3 = u2 * u;
        float b0 = um * um * um * (1.0f / 6.0f);
        float b1 = (3.0f * u3 - 6.0f * u2 + 4.0f) * (1.0f / 6.0f);
        float b2 = (-3.0f * u3 + 3.0f * u2 + 3.0f * u + 1.0f) * (1.0f / 6.0f);
        float b3 = u3 * (1.0f / 6.0f);

        __half2 p01 = __floats2half2_rn(b0, b1);
        __half2 p23 = __floats2half2_rn(b2, b3);
        uint64_t v64 = (uint64_t)reinterpret_cast<uint32_t&>(p01) |
                       ((uint64_t)reinterpret_cast<uint32_t&>(p23) << 32);
        int sh = (t & 3) * 16;
        uint64_t rot = sh ? ((v64 << sh) | (v64 >> (64 - sh))) : v64;
        if (t >= 5) rot &= (~0ull) << ((t - 4) * 16);
        uint8_t meta = 0x44;
        if (valid) meta = (uint8_t)(META_TAB >> (t * 8));
        else       rot = 0ull;

        *reinterpret_cast<uint2*>(g_Ab + (size_t)row * 2048 + (size_t)i * 4) =
            make_uint2((uint32_t)rot, (uint32_t)(rot >> 32));
        g_metaB[(size_t)row * 512 + i] = meta;
    }
}

// ============================================================================
// gen_W: base panel + permuted spline panel (Wb[o][i*8+p] = sp[(p&1)*4+(p>>1)])
// ============================================================================
__global__ void gen_W_kernel(const float* __restrict__ bw, const float* __restrict__ sw) {
    int o = blockIdx.x;
    int i = threadIdx.x;
    g_Ws[(size_t)o * 512 + i] = __float2half(bw[(size_t)o * 512 + i]);
    const float* sp = sw + ((size_t)o * 512 + i) * 8;
    __half h[8];
#pragma unroll
    for (int p = 0; p < 8; ++p) h[p] = __float2half(sp[(p & 1) * 4 + (p >> 1)]);
    *reinterpret_cast<uint4*>(g_Wb + (size_t)o * 4096 + (size_t)i * 8) =
        *reinterpret_cast<const uint4*>(h);
}

// ============================================================================
// meta_pack: g_metaB[b][i] -> g_metaP[(k16*1024 + M16)*8 + q]
// ============================================================================
__global__ __launch_bounds__(256) void meta_pack_kernel() {
    int g = blockIdx.x * 256 + threadIdx.x;     // 262144 total
    int k16 = g & 255, M16 = g >> 8;
    uint32_t w[8];
#pragma unroll
    for (int q = 0; q < 8; ++q) {
        int b0 = M16 * 16 + q;
        uint32_t lo = *reinterpret_cast<const uint16_t*>(g_metaB + (size_t)b0 * 512 + k16 * 2);
        uint32_t hi = *reinterpret_cast<const uint16_t*>(g_metaB + (size_t)(b0 + 8) * 512 + k16 * 2);
        w[q] = lo | (hi << 16);
    }
    uint32_t* dst = g_metaP + ((size_t)k16 * 1024 + M16) * 8;
    *reinterpret_cast<uint4*>(dst)     = make_uint4(w[0], w[1], w[2], w[3]);
    *reinterpret_cast<uint4*>(dst + 4) = make_uint4(w[4], w[5], w[6], w[7]);
}

// ============================================================================
// GEMM: CTA 256x128, 16 warps (4M x 4N grid, warp tile 64x32), 3-stage.
// ============================================================================
__device__ __forceinline__ void load_stage_sp(uint32_t sb, int s, int kt,
                                              int mbase, int nbase, int tid) {
    uint32_t stage = sb + s * STAGE_BYTES;
    const __half* agp = g_Ab + (size_t)mbase * 2048 + kt * 64;
#pragma unroll
    for (int it = 0; it < 4; ++it) {          // A: 256 rows x 128B
        int c = tid + it * NTHREADS;
        int row = c >> 3, col = c & 7;
        cp_async16(stage + SWZ((uint32_t)(row * 128 + col * 16)),
                   agp + (size_t)row * 2048 + col * 8);
    }
    uint32_t bb = stage + SA_BYTES;
#pragma unroll
    for (int it = 0; it < 4; ++it) {          // B: 256 mem-rows x 128B
        int c = tid + it * NTHREADS;
        int r = c >> 3, col = c & 7;
        cp_async16(bb + SWZ((uint32_t)(r * 128 + col * 16)),
                   g_Wb + (size_t)(nbase + (r >> 1)) * 4096 + kt * 128 + (r & 1) * 64 + col * 8);
    }
    if (tid < 256) {                          // meta: 8 k16 x 16 M16 x 8 q words = 4KB
        int k16l = tid >> 5, m = (tid & 31) >> 1, q0 = (tid & 1) * 4;
        const char* src = (const char*)(g_metaP +
            ((size_t)(kt * 8 + k16l) * 1024 + (mbase >> 4) + m) * 8 + q0);
        cp_async16(stage + SA_BYTES + SB_BYTES + tid * 16, src);
    }
}

__device__ __forceinline__ void load_stage_dn(uint32_t sb, int s, int ktd,
                                              int mbase, int nbase, int tid) {
    uint32_t stage = sb + s * STAGE_BYTES;
#pragma unroll
    for (int it = 0; it < 4; ++it) {          // A dense: 256 rows x 128B
        int c = tid + it * NTHREADS;
        int row = c >> 3, col = c & 7;
        cp_async16(stage + SWZ((uint32_t)(row * 128 + col * 16)),
                   g_As + (size_t)(mbase + row) * 512 + ktd * 64 + col * 8);
    }
    uint32_t bb = stage + SA_BYTES;
#pragma unroll
    for (int it = 0; it < 2; ++it) {          // B dense: 128 rows x 128B
        int c = tid + it * NTHREADS;
        int row = c >> 3, col = c & 7;
        cp_async16(bb + SWZ((uint32_t)(row * 128 + col * 16)),
                   g_Ws + (size_t)(nbase + row) * 512 + ktd * 64 + col * 8);
    }
}

__global__ __launch_bounds__(NTHREADS, 1) void kan_gemm_kernel(float* __restrict__ out) {
    extern __shared__ __align__(1024) char smem[];
    uint32_t sb = smem_u32(smem);
    int tid = threadIdx.x, wid = tid >> 5, lane = tid & 31;
    int mbase = blockIdx.y * BM, nbase = blockIdx.x * BN;
    int warp_m = wid & 3;            // 4 warp-rows of 64
    int warp_n = wid >> 2;           // 4 warp-cols of 32

    float acc[4][4][4];
#pragma unroll
    for (int i = 0; i < 4; ++i)
#pragma unroll
        for (int jj = 0; jj < 4; ++jj)
#pragma unroll
            for (int q = 0; q < 4; ++q) acc[i][jj][q] = 0.0f;

    int a_row_in_tile = (lane & 7) + ((lane >> 3) & 1) * 8;
    int a_byte = (lane >> 4) * 16;
    int b_row_in_pair = (lane & 7) + (lane >> 4) * 8;
    int b_byte = ((lane >> 3) & 1) * 16;
    int qid = lane >> 2, tp1 = lane & 1;

#pragma unroll
    for (int p = 0; p < STAGES - 1; ++p) { load_stage_sp(sb, p, p, mbase, nbase, tid); cp_commit(); }

    for (int kt = 0; kt < NKIT; ++kt) {
        int s = kt % STAGES;
        cp_wait<STAGES - 2>();
        __syncthreads();
        int kload = kt + STAGES - 1;
        if (kload < NKIT) {
            if (kload < NSP) load_stage_sp(sb, kload % STAGES, kload, mbase, nbase, tid);
            else             load_stage_dn(sb, kload % STAGES, kload - NSP, mbase, nbase, tid);
        }
        cp_commit();

        uint32_t astage = sb + s * STAGE_BYTES;
        uint32_t bstage = astage + SA_BYTES;
        if (kt < NSP) {
            uint32_t mstage = astage + SA_BYTES + SB_BYTES;
#pragma unroll
            for (int j = 0; j < 4; ++j) {
                uint32_t a[4][4];
#pragma unroll
                for (int mt = 0; mt < 4; ++mt) {
                    int row = warp_m * 64 + mt * 16 + a_row_in_tile;
                    ldsm_x4(a[mt][0], a[mt][1], a[mt][2], a[mt][3],
                            astage + SWZ((uint32_t)(row * 128 + j * 32 + a_byte)));
                }
                uint32_t b[4][4];
#pragma unroll
                for (int pr = 0; pr < 2; ++pr) {
                    int rm = (warp_n * 32 + pr * 16 + b_row_in_pair) * 2 + (j >> 1);
                    uint32_t kb = (uint32_t)((j & 1) * 64 + b_byte);
                    uint32_t l0, l1, l2, l3, h0, h1, h2, h3;
                    ldsm_x4(l0, l1, l2, l3, bstage + SWZ((uint32_t)(rm * 128) + kb));
                    ldsm_x4(h0, h1, h2, h3, bstage + SWZ((uint32_t)(rm * 128) + kb + 32));
                    b[pr * 2 + 0][0] = l0; b[pr * 2 + 0][1] = l1;
                    b[pr * 2 + 0][2] = h0; b[pr * 2 + 0][3] = h1;
                    b[pr * 2 + 1][0] = l2; b[pr * 2 + 1][1] = l3;
                    b[pr * 2 + 1][2] = h2; b[pr * 2 + 1][3] = h3;
                }
#pragma unroll
                for (int mt = 0; mt < 4; ++mt) {
                    int m16c = warp_m * 4 + mt;
                    uint32_t em;
                    uint32_t widx = (uint32_t)((((j * 2 + tp1) * 16 + m16c) * 8 + qid) * 4);
                    asm volatile("ld.shared.b32 %0, [%1];" : "=r"(em) : "r"(mstage + widx));
#pragma unroll
                    for (int nt = 0; nt < 4; ++nt)
                        mma_sp(acc[mt][nt][0], acc[mt][nt][1], acc[mt][nt][2], acc[mt][nt][3],
                               a[mt][0], a[mt][1], a[mt][2], a[mt][3],
                               b[nt][0], b[nt][1], b[nt][2], b[nt][3], em);
                }
            }
        } else {
#pragma unroll
            for (int ks = 0; ks < 4; ++ks) {
                int kbyte = ks * 32;
                uint32_t a[4][4];
#pragma unroll
                for (int mt = 0; mt < 4; ++mt) {
                    int row = warp_m * 64 + mt * 16 + a_row_in_tile;
                    ldsm_x4(a[mt][0], a[mt][1], a[mt][2], a[mt][3],
                            astage + SWZ((uint32_t)(row * 128 + kbyte + a_byte)));
                }
                uint32_t b[4][2];
#pragma unroll
                for (int pr = 0; pr < 2; ++pr) {
                    int row = warp_n * 32 + pr * 16 + b_row_in_pair;
                    uint32_t r0, r1, r2, r3;
                    ldsm_x4(r0, r1, r2, r3, bstage + SWZ((uint32_t)(row * 128 + kbyte + b_byte)));
                    b[pr * 2 + 0][0] = r0; b[pr * 2 + 0][1] = r1;
                    b[pr * 2 + 1][0] = r2; b[pr * 2 + 1][1] = r3;
                }
#pragma unroll
                for (int mt = 0; mt < 4; ++mt)
#pragma unroll
                    for (int nt = 0; nt < 4; ++nt)
                        mma16816(acc[mt][nt][0], acc[mt][nt][1], acc[mt][nt][2], acc[mt][nt][3],
                                 a[mt][0], a[mt][1], a[mt][2], a[mt][3],
                                 b[nt][0], b[nt][1]);
            }
        }
    }

    int r0 = mbase + warp_m * 64 + (lane >> 2);
    int c0 = nbase + warp_n * 32 + (lane & 3) * 2;
#pragma unroll
    for (int mt = 0; mt < 4; ++mt) {
#pragma unroll
        for (int nt = 0; nt < 4; ++nt) {
            float* p = out + (size_t)(r0 + mt * 16) * O_SZ + c0 + nt * 8;
            *reinterpret_cast<float2*>(p) = make_float2(acc[mt][nt][0], acc[mt][nt][1]);
            float* p2 = p + 8 * O_SZ;
            *reinterpret_cast<float2*>(p2) = make_float2(acc[mt][nt][2], acc[mt][nt][3]);
        }
    }
}

// ============================================================================
extern "C" void kernel_launch(void* const* d_in, const int* in_sizes, int n_in,
                              void* d_out, int out_size) {
    const float* x  = (const float*)d_in[0];
    const float* bw = (const float*)d_in[1];
    const float* sw = (const float*)d_in[2];
    float* out = (float*)d_out;

    cudaFuncSetAttribute(kan_gemm_kernel,
                         cudaFuncAttributeMaxDynamicSharedMemorySize, SMEM_BYTES);

    gen_A_kernel<<<B_SZ / 4, 256>>>(x);
    gen_W_kernel<<<O_SZ, 512>>>(bw, sw);
    meta_pack_kernel<<<1024, 256>>>();

    dim3 grid(O_SZ / BN, B_SZ / BM);   // (4, 64)
    kan_gemm_kernel<<<grid, NTHREADS, SMEM_BYTES>>>(out);
}